// round 9
// baseline (speedup 1.0000x reference)
#include <cuda_runtime.h>
#include <cuda_fp16.h>
#include <cstdint>

#define NN 50000
#define NE 800000
#define FIN 128
#define H1DIM 256   // NHEAD*NHID
#define NH1 4
#define NB 8
#define NC 40

typedef unsigned long long ull;

__device__ __forceinline__ ull dup2f(float x) {
    unsigned u = __float_as_uint(x);
    ull r; asm("mov.b64 %0, {%1, %1};" : "=l"(r) : "r"(u)); return r;
}
__device__ __forceinline__ void ffma2(ull& d, ull a, ull b) {
    asm("fma.rn.f32x2 %0, %1, %2, %0;" : "+l"(d) : "l"(a), "l"(b));
}
__device__ __forceinline__ float2 unpk(ull v) {
    unsigned lo, hi;
    asm("mov.b64 {%0, %1}, %2;" : "=r"(lo), "=r"(hi) : "l"(v));
    return make_float2(__uint_as_float(lo), __uint_as_float(hi));
}
__device__ __forceinline__ ull pk2(float x, float y) {
    ull r;
    asm("mov.b64 %0, {%1, %2};" : "=l"(r) : "r"(__float_as_uint(x)), "r"(__float_as_uint(y)));
    return r;
}
// two f16 packed in u -> packed f32x2
__device__ __forceinline__ ull h2f2(unsigned u) {
    float2 f = __half22float2(*(__half2*)&u);
    return pk2(f.x, f.y);
}

// ---------------- scratch (device globals; allocation-free) ----------------
__device__ __half g_h1h[(size_t)NN * H1DIM];  // x @ W1 (fp16)
__device__ float  g_o1[(size_t)NN * H1DIM];   // layer-1 out (fp32)
__device__ __half g_h2h[(size_t)NN * NC];     // o1 @ W2 (fp16)
__device__ float g_es1[NN * NH1], g_ed1[NN * NH1];
__device__ float g_es2[NN], g_ed2[NN];
__device__ int   g_deg[NN];
__device__ int   g_off[NN + 1];
__device__ int   g_cur[NN];
__device__ int   g_csrc[NE];
__device__ float g_M1s[FIN * NH1], g_M1d[FIN * NH1];
__device__ float g_M2s[H1DIM], g_M2d[H1DIM];
__device__ int   g_is64;

// ---------------- misc ----------------
__global__ void k_misc(const void* ei, const float* __restrict__ B1,
                       const float* __restrict__ cs1, const float* __restrict__ cd1,
                       const float* __restrict__ B2, const float* __restrict__ cs2,
                       const float* __restrict__ cd2) {
    int tid = threadIdx.x;
    if (tid == 0) {
        const unsigned* w = (const unsigned*)ei;
        int is64 = 1;
        for (int i = 0; i < 64; i++) {
            if (w[2 * i + 1] != 0u) { is64 = 0; break; }
        }
        g_is64 = is64;
    }
    for (int i = tid; i < FIN * NH1; i += blockDim.x) {
        int k = i / NH1, h = i % NH1;
        float ss = 0.f, sd = 0.f;
        for (int j = 0; j < NB; j++) {
            float b = B1[k * NB + j];
            ss += b * cs1[j * NH1 + h];
            sd += b * cd1[j * NH1 + h];
        }
        g_M1s[i] = ss; g_M1d[i] = sd;
    }
    for (int i = tid; i < H1DIM; i += blockDim.x) {
        float ss = 0.f, sd = 0.f;
        for (int j = 0; j < NB; j++) {
            float b = B2[i * NB + j];
            ss += b * cs2[j];
            sd += b * cd2[j];
        }
        g_M2s[i] = ss; g_M2d[i] = sd;
    }
    for (int i = tid; i < NN; i += blockDim.x) g_deg[i] = 0;
}

// ---------------- CSR build (32-bit loads only) ----------------
__global__ void k_hist(const void* ei) {
    int e = blockIdx.x * blockDim.x + threadIdx.x;
    if (e >= NE) return;
    const int* p = (const int*)ei;
    int d = g_is64 ? p[2 * (NE + e)] : p[NE + e];
    atomicAdd(&g_deg[d], 1);
}

__global__ void k_scan() {  // single block, 1024 threads
    __shared__ int part[1024];
    int tid = threadIdx.x;
    const int per = (NN + 1023) / 1024;
    int start = tid * per;
    int end = start + per; if (end > NN) end = NN;
    if (start > NN) start = NN;
    int s = 0;
    for (int i = start; i < end; i++) s += g_deg[i];
    part[tid] = s;
    __syncthreads();
    for (int off = 1; off < 1024; off <<= 1) {
        int v = (tid >= off) ? part[tid - off] : 0;
        __syncthreads();
        part[tid] += v;
        __syncthreads();
    }
    int run = (tid > 0) ? part[tid - 1] : 0;
    for (int i = start; i < end; i++) {
        g_off[i] = run; g_cur[i] = run;
        run += g_deg[i];
    }
    if (tid == 1023) g_off[NN] = part[1023];
}

__global__ void k_scatter(const void* ei) {
    int e = blockIdx.x * blockDim.x + threadIdx.x;
    if (e >= NE) return;
    const int* p = (const int*)ei;
    int s, d;
    if (g_is64) { s = p[2 * e]; d = p[2 * (NE + e)]; }
    else        { s = p[e];     d = p[NE + e]; }
    int pos = atomicAdd(&g_cur[d], 1);
    g_csrc[pos] = s;
}

// ---------------- HMMA GEMM1: h1(fp16) = x(f32->f16) @ W1(f32->f16) -------
// Block tile 64(m) x 64(n), K=128 whole. 256 threads = 8 warps (4x2),
// warp tile 16(m) x 32(n). fp32 accumulate, fp16 store.
__global__ __launch_bounds__(256) void gemm1_hmma(const float* __restrict__ A,
                                                  const float* __restrict__ B,
                                                  __half* __restrict__ C) {
    __shared__ __half As[64][136];   // 272B row stride = 17x16B (odd) -> LDSM conflict-free
    __shared__ __half Bs[128][72];   // 144B row stride = 9x16B (odd)
    int tid = threadIdx.x;
    int row0 = blockIdx.y * 64, col0 = blockIdx.x * 64;

    // load A tile 64x128 (f32 -> f16)
#pragma unroll
    for (int it = 0; it < 8; it++) {
        int idx = tid + it * 256;
        int r = idx >> 5, c4 = (idx & 31) << 2;
        int gr = row0 + r;
        float4 v = make_float4(0.f, 0.f, 0.f, 0.f);
        if (gr < NN) v = *(const float4*)&A[(size_t)gr * FIN + c4];
        *(__half2*)&As[r][c4]     = __floats2half2_rn(v.x, v.y);
        *(__half2*)&As[r][c4 + 2] = __floats2half2_rn(v.z, v.w);
    }
    // load B slice 128x64 (f32 -> f16)
#pragma unroll
    for (int it = 0; it < 8; it++) {
        int idx = tid + it * 256;
        int r = idx >> 4, c4 = (idx & 15) << 2;
        float4 v = *(const float4*)&B[(size_t)r * H1DIM + col0 + c4];
        *(__half2*)&Bs[r][c4]     = __floats2half2_rn(v.x, v.y);
        *(__half2*)&Bs[r][c4 + 2] = __floats2half2_rn(v.z, v.w);
    }
    __syncthreads();

    int wid = tid >> 5, lane = tid & 31;
    int m0 = (wid & 3) * 16, n0 = (wid >> 2) * 32;

    float d[4][4];
#pragma unroll
    for (int nt = 0; nt < 4; nt++)
#pragma unroll
        for (int i = 0; i < 4; i++) d[nt][i] = 0.f;

    unsigned as_base = (unsigned)__cvta_generic_to_shared(
        &As[m0 + (lane & 15)][(lane >> 4) << 3]);
    int brow = lane & 15;

#pragma unroll
    for (int ks = 0; ks < 8; ks++) {
        int k0 = ks * 16;
        unsigned a0, a1, a2, a3;
        asm volatile("ldmatrix.sync.aligned.m8n8.x4.shared.b16 {%0,%1,%2,%3}, [%4];"
                     : "=r"(a0), "=r"(a1), "=r"(a2), "=r"(a3)
                     : "r"(as_base + k0 * 2));
#pragma unroll
        for (int nt = 0; nt < 4; nt++) {
            unsigned baddr = (unsigned)__cvta_generic_to_shared(
                &Bs[k0 + brow][n0 + nt * 8]);
            unsigned b0, b1;
            asm volatile("ldmatrix.sync.aligned.m8n8.x2.trans.shared.b16 {%0,%1}, [%2];"
                         : "=r"(b0), "=r"(b1) : "r"(baddr));
            asm volatile("mma.sync.aligned.m16n8k16.row.col.f32.f16.f16.f32 "
                         "{%0,%1,%2,%3}, {%4,%5,%6,%7}, {%8,%9}, {%0,%1,%2,%3};"
                         : "+f"(d[nt][0]), "+f"(d[nt][1]), "+f"(d[nt][2]), "+f"(d[nt][3])
                         : "r"(a0), "r"(a1), "r"(a2), "r"(a3), "r"(b0), "r"(b1));
        }
    }
    // store: lane holds rows (lane>>2, +8), cols (lane&3)*2 per n-tile
    int r0 = row0 + m0 + (lane >> 2);
    int cb = col0 + n0 + (lane & 3) * 2;
#pragma unroll
    for (int nt = 0; nt < 4; nt++) {
        int c = cb + nt * 8;
        if (r0 < NN)
            *(__half2*)&C[(size_t)r0 * H1DIM + c] = __floats2half2_rn(d[nt][0], d[nt][1]);
        if (r0 + 8 < NN)
            *(__half2*)&C[(size_t)(r0 + 8) * H1DIM + c] = __floats2half2_rn(d[nt][2], d[nt][3]);
    }
}

// ---------------- f32x2 tiled GEMM (FFMA2), fp16 output — used for layer 2 -
__global__ __launch_bounds__(256) void gemm_f16out(const float* __restrict__ A,
                                                   const float* __restrict__ B,
                                                   __half* __restrict__ C,
                                                   int M, int N, int K) {
    __shared__ __align__(16) float As[16][130];   // [kk][m]
    __shared__ __align__(16) float Bs[16][68];    // [kk][n]
    int tid = threadIdx.x;
    int tx = tid & 15, ty = tid >> 4;
    int row0 = blockIdx.y * 128, col0 = blockIdx.x * 64;

    ull acc[4][4];
#pragma unroll
    for (int i = 0; i < 4; i++)
#pragma unroll
        for (int j = 0; j < 4; j++) acc[i][j] = 0ull;

    for (int k0 = 0; k0 < K; k0 += 16) {
        {
            int r = tid >> 2;            // 0..63
            int c4 = (tid & 3) * 4;      // 0,4,8,12
#pragma unroll
            for (int rr = 0; rr < 2; rr++) {
                int row = r + rr * 64;
                int gr = row0 + row;
                float4 v = make_float4(0.f, 0.f, 0.f, 0.f);
                if (gr < M) v = *(const float4*)&A[(size_t)gr * K + k0 + c4];
                As[c4 + 0][row] = v.x; As[c4 + 1][row] = v.y;
                As[c4 + 2][row] = v.z; As[c4 + 3][row] = v.w;
            }
        }
        {
            int r = tid >> 4;            // 0..15
            int c4 = (tid & 15) * 4;
            int gc = col0 + c4;
            float4 v;
            if (gc + 3 < N) {
                v = *(const float4*)&B[(size_t)(k0 + r) * N + gc];
            } else {
                v.x = (gc + 0 < N) ? B[(size_t)(k0 + r) * N + gc + 0] : 0.f;
                v.y = (gc + 1 < N) ? B[(size_t)(k0 + r) * N + gc + 1] : 0.f;
                v.z = (gc + 2 < N) ? B[(size_t)(k0 + r) * N + gc + 2] : 0.f;
                v.w = (gc + 3 < N) ? B[(size_t)(k0 + r) * N + gc + 3] : 0.f;
            }
            *(float4*)&Bs[r][c4] = v;
        }
        __syncthreads();
#pragma unroll
        for (int kk = 0; kk < 16; kk++) {
            float4 bq = *(const float4*)&Bs[kk][tx * 4];
            ull bd0 = dup2f(bq.x), bd1 = dup2f(bq.y), bd2 = dup2f(bq.z), bd3 = dup2f(bq.w);
            ull av[4];
#pragma unroll
            for (int i = 0; i < 4; i++)
                av[i] = *(const ull*)&As[kk][ty * 8 + 2 * i];
#pragma unroll
            for (int i = 0; i < 4; i++) {
                ffma2(acc[i][0], av[i], bd0);
                ffma2(acc[i][1], av[i], bd1);
                ffma2(acc[i][2], av[i], bd2);
                ffma2(acc[i][3], av[i], bd3);
            }
        }
        __syncthreads();
    }
    int gc = col0 + tx * 4;
    if (gc + 4 <= N) {
#pragma unroll
        for (int i = 0; i < 4; i++) {
            float2 c0 = unpk(acc[i][0]);
            float2 c1 = unpk(acc[i][1]);
            float2 c2 = unpk(acc[i][2]);
            float2 c3 = unpk(acc[i][3]);
            int gr0 = row0 + ty * 8 + 2 * i;
#pragma unroll
            for (int p = 0; p < 2; p++) {
                int gr = gr0 + p;
                if (gr >= M) continue;
                float f0 = p ? c0.y : c0.x, f1 = p ? c1.y : c1.x;
                float f2 = p ? c2.y : c2.x, f3 = p ? c3.y : c3.x;
                unsigned u0, u1;
                asm("cvt.rn.f16x2.f32 %0, %1, %2;" : "=r"(u0) : "f"(f1), "f"(f0));
                asm("cvt.rn.f16x2.f32 %0, %1, %2;" : "=r"(u1) : "f"(f3), "f"(f2));
                *(uint2*)(C + (size_t)gr * N + gc) = make_uint2(u0, u1);
            }
        }
    }
}

// ---------------- per-node attention logits, layer 1 ----------------
__global__ void k_ef1(const float* __restrict__ x) {
    __shared__ float xs[32][FIN + 4];
    __shared__ float M1[2][FIN * NH1];
    int n0 = blockIdx.x * 32;
    int tid = threadIdx.x;  // 256
    for (int i = tid; i < FIN * NH1; i += 256) {
        M1[0][i] = g_M1s[i];
        M1[1][i] = g_M1d[i];
    }
    for (int i = tid; i < 32 * FIN; i += 256) {
        int r = i / FIN, c = i % FIN;
        int gn = n0 + r;
        xs[r][c] = (gn < NN) ? x[(size_t)gn * FIN + c] : 0.f;
    }
    __syncthreads();
    int node = tid / 8, q = tid % 8;
    int h = q & 3;
    int isd = q >> 2;
    const float* M = M1[isd];
    float s = 0.f;
#pragma unroll 16
    for (int k = 0; k < FIN; k++) s += xs[node][k] * M[k * NH1 + h];
    int gn = n0 + node;
    if (gn < NN) {
        if (isd) g_ed1[gn * NH1 + h] = s;
        else     g_es1[gn * NH1 + h] = s;
    }
}

// ---------------- layer-1 aggregation: 1 warp per dst node -----------------
__global__ void k_agg1(const float* __restrict__ b1) {
    int warp = (blockIdx.x * blockDim.x + threadIdx.x) >> 5;
    if (warp >= NN) return;
    int lane = threadIdx.x & 31;
    int node = warp;
    int head = lane >> 3;
    int f0 = lane * 8;
    ull a2[4] = {0ull, 0ull, 0ull, 0ull};
    float s = 0.f;
    float edv = g_ed1[node * NH1 + head];
    int beg = g_off[node], end = g_off[node + 1];
    int src_n = (beg < end) ? g_csrc[beg] : 0;
    for (int j = beg; j < end; j++) {
        int src = src_n;
        if (j + 1 < end) src_n = g_csrc[j + 1];
        float e = g_es1[src * NH1 + head] + edv;
        e = (e > 0.f) ? e : 0.2f * e;                 // leaky_relu
        float w = __expf(e);
        s += w;
        ull wd = dup2f(w);
        uint4 hv = *(const uint4*)(g_h1h + (size_t)src * H1DIM + f0);
        ffma2(a2[0], wd, h2f2(hv.x));
        ffma2(a2[1], wd, h2f2(hv.y));
        ffma2(a2[2], wd, h2f2(hv.z));
        ffma2(a2[3], wd, h2f2(hv.w));
    }
    float inv = 1.f / (s + 1e-16f);
    float o[8];
#pragma unroll
    for (int p = 0; p < 4; p++) {
        float2 v = unpk(a2[p]);
        o[2 * p + 0] = v.x; o[2 * p + 1] = v.y;
    }
    float4 q0, q1;
#pragma unroll
    for (int i = 0; i < 8; i++) {
        float v = o[i] * inv + b1[f0 + i];
        v = (v > 0.f) ? v : (__expf(v) - 1.f);        // ELU
        if (i < 4) (&q0.x)[i] = v; else (&q1.x)[i - 4] = v;
    }
    float4* op = (float4*)(g_o1 + (size_t)node * H1DIM + f0);
    op[0] = q0; op[1] = q1;
}

// ---------------- per-node attention logits, layer 2 ----------------
__global__ void k_ef2() {
    int warp = (blockIdx.x * blockDim.x + threadIdx.x) >> 5;
    if (warp >= NN) return;
    int lane = threadIdx.x & 31;
    const float* row = g_o1 + (size_t)warp * H1DIM;
    float ps = 0.f, pd = 0.f;
#pragma unroll
    for (int i = 0; i < 8; i++) {
        int k = lane + 32 * i;
        float v = row[k];
        ps += v * g_M2s[k];
        pd += v * g_M2d[k];
    }
#pragma unroll
    for (int o = 16; o > 0; o >>= 1) {
        ps += __shfl_xor_sync(0xffffffffu, ps, o);
        pd += __shfl_xor_sync(0xffffffffu, pd, o);
    }
    if (lane == 0) { g_es2[warp] = ps; g_ed2[warp] = pd; }
}

// ---------------- layer-2 aggregation: warp per dst node -------------------
__global__ void k_agg2(float* __restrict__ out) {
    int warp = (blockIdx.x * blockDim.x + threadIdx.x) >> 5;
    if (warp >= NN) return;
    int lane = threadIdx.x & 31;
    int node = warp;
    float a0 = 0.f, a1 = 0.f, s = 0.f;
    float edv = g_ed2[node];
    int beg = g_off[node], end = g_off[node + 1];
    int src_n = (beg < end) ? g_csrc[beg] : 0;
    for (int j = beg; j < end; j++) {
        int src = src_n;
        if (j + 1 < end) src_n = g_csrc[j + 1];
        float e = g_es2[src] + edv;
        e = (e > 0.f) ? e : 0.2f * e;
        float w = __expf(e);
        float v0 = __half2float(g_h2h[(size_t)src * NC + lane]);
        float v1 = (lane < 8) ? __half2float(g_h2h[(size_t)src * NC + 32 + lane]) : 0.f;
        s += w;
        a0 += w * v0;
        a1 += w * v1;
    }
    float inv = 1.f / (s + 1e-16f);
    out[(size_t)node * NC + lane] = a0 * inv;
    if (lane < 8) out[(size_t)node * NC + 32 + lane] = a1 * inv;
}

// ---------------- host launcher ----------------
extern "C" void kernel_launch(void* const* d_in, const int* in_sizes, int n_in,
                              void* d_out, int out_size) {
    const float* x   = (const float*)d_in[0];
    const void*  ei  = d_in[1];
    const float* W1  = (const float*)d_in[2];
    const float* b1  = (const float*)d_in[3];
    const float* B1  = (const float*)d_in[4];
    const float* cs1 = (const float*)d_in[5];
    const float* cd1 = (const float*)d_in[6];
    const float* W2  = (const float*)d_in[7];
    const float* B2  = (const float*)d_in[8];
    const float* cs2 = (const float*)d_in[9];
    const float* cd2 = (const float*)d_in[10];
    float* out = (float*)d_out;

    void *p_h1 = nullptr, *p_o1 = nullptr, *p_h2 = nullptr;
    cudaGetSymbolAddress(&p_h1, g_h1h);
    cudaGetSymbolAddress(&p_o1, g_o1);
    cudaGetSymbolAddress(&p_h2, g_h2h);

    k_misc<<<1, 512>>>(ei, B1, cs1, cd1, B2, cs2, cd2);
    k_hist<<<(NE + 255) / 256, 256>>>(ei);
    k_scan<<<1, 1024>>>();
    k_scatter<<<(NE + 255) / 256, 256>>>(ei);

    // layer 1
    gemm1_hmma<<<dim3(H1DIM / 64, (NN + 63) / 64), 256>>>(x, W1, (__half*)p_h1);
    k_ef1<<<(NN + 31) / 32, 256>>>(x);
    k_agg1<<<(NN + 7) / 8, 256>>>(b1);

    // layer 2
    gemm_f16out<<<dim3(1, (NN + 127) / 128), 256>>>((const float*)p_o1, W2,
                                                    (__half*)p_h2, NN, NC, H1DIM);
    k_ef2<<<(NN + 7) / 8, 256>>>();
    k_agg2<<<(NN + 7) / 8, 256>>>(out);
}

// round 10
// speedup vs baseline: 1.3179x; 1.3179x over previous
#include <cuda_runtime.h>
#include <cuda_fp16.h>
#include <cstdint>

#define NN 50000
#define NE 800000
#define FIN 128
#define H1DIM 256   // NHEAD*NHID
#define NH1 4
#define NB 8
#define NC 40

typedef unsigned long long ull;

__device__ __forceinline__ ull dup2f(float x) {
    unsigned u = __float_as_uint(x);
    ull r; asm("mov.b64 %0, {%1, %1};" : "=l"(r) : "r"(u)); return r;
}
__device__ __forceinline__ void ffma2(ull& d, ull a, ull b) {
    asm("fma.rn.f32x2 %0, %1, %2, %0;" : "+l"(d) : "l"(a), "l"(b));
}
__device__ __forceinline__ float2 unpk(ull v) {
    unsigned lo, hi;
    asm("mov.b64 {%0, %1}, %2;" : "=r"(lo), "=r"(hi) : "l"(v));
    return make_float2(__uint_as_float(lo), __uint_as_float(hi));
}
__device__ __forceinline__ ull pk2(float x, float y) {
    ull r;
    asm("mov.b64 %0, {%1, %2};" : "=l"(r) : "r"(__float_as_uint(x)), "r"(__float_as_uint(y)));
    return r;
}
// two f16 packed in u -> packed f32x2
__device__ __forceinline__ ull h2f2(unsigned u) {
    float2 f = __half22float2(*(__half2*)&u);
    return pk2(f.x, f.y);
}

// ---------------- scratch (device globals; allocation-free) ----------------
__device__ __half g_h1h[(size_t)NN * H1DIM];  // x @ W1 (fp16)
__device__ float  g_o1[(size_t)NN * H1DIM];   // layer-1 out (fp32)
__device__ __half g_h2h[(size_t)NN * NC];     // o1 @ W2 (fp16)
__device__ float g_es1[NN * NH1], g_ed1[NN * NH1];
__device__ float g_es2[NN], g_ed2[NN];
__device__ int   g_deg[NN];
__device__ int   g_off[NN + 1];
__device__ int   g_cur[NN];
__device__ int   g_csrc[NE];
__device__ float g_M1s[FIN * NH1], g_M1d[FIN * NH1];
__device__ float g_M2s[H1DIM], g_M2d[H1DIM];
__device__ int   g_is64;

// ---------------- misc ----------------
__global__ void k_misc(const void* ei, const float* __restrict__ B1,
                       const float* __restrict__ cs1, const float* __restrict__ cd1,
                       const float* __restrict__ B2, const float* __restrict__ cs2,
                       const float* __restrict__ cd2) {
    int tid = threadIdx.x;
    if (tid == 0) {
        const unsigned* w = (const unsigned*)ei;
        int is64 = 1;
        for (int i = 0; i < 64; i++) {
            if (w[2 * i + 1] != 0u) { is64 = 0; break; }
        }
        g_is64 = is64;
    }
    for (int i = tid; i < FIN * NH1; i += blockDim.x) {
        int k = i / NH1, h = i % NH1;
        float ss = 0.f, sd = 0.f;
        for (int j = 0; j < NB; j++) {
            float b = B1[k * NB + j];
            ss += b * cs1[j * NH1 + h];
            sd += b * cd1[j * NH1 + h];
        }
        g_M1s[i] = ss; g_M1d[i] = sd;
    }
    for (int i = tid; i < H1DIM; i += blockDim.x) {
        float ss = 0.f, sd = 0.f;
        for (int j = 0; j < NB; j++) {
            float b = B2[i * NB + j];
            ss += b * cs2[j];
            sd += b * cd2[j];
        }
        g_M2s[i] = ss; g_M2d[i] = sd;
    }
    for (int i = tid; i < NN; i += blockDim.x) g_deg[i] = 0;
}

// ---------------- CSR build (32-bit loads only) ----------------
__global__ void k_hist(const void* ei) {
    int e = blockIdx.x * blockDim.x + threadIdx.x;
    if (e >= NE) return;
    const int* p = (const int*)ei;
    int d = g_is64 ? p[2 * (NE + e)] : p[NE + e];
    atomicAdd(&g_deg[d], 1);
}

__global__ void k_scan() {  // single block, 1024 threads
    __shared__ int part[1024];
    int tid = threadIdx.x;
    const int per = (NN + 1023) / 1024;
    int start = tid * per;
    int end = start + per; if (end > NN) end = NN;
    if (start > NN) start = NN;
    int s = 0;
    for (int i = start; i < end; i++) s += g_deg[i];
    part[tid] = s;
    __syncthreads();
    for (int off = 1; off < 1024; off <<= 1) {
        int v = (tid >= off) ? part[tid - off] : 0;
        __syncthreads();
        part[tid] += v;
        __syncthreads();
    }
    int run = (tid > 0) ? part[tid - 1] : 0;
    for (int i = start; i < end; i++) {
        g_off[i] = run; g_cur[i] = run;
        run += g_deg[i];
    }
    if (tid == 1023) g_off[NN] = part[1023];
}

__global__ void k_scatter(const void* ei) {
    int e = blockIdx.x * blockDim.x + threadIdx.x;
    if (e >= NE) return;
    const int* p = (const int*)ei;
    int s, d;
    if (g_is64) { s = p[2 * e]; d = p[2 * (NE + e)]; }
    else        { s = p[e];     d = p[NE + e]; }
    int pos = atomicAdd(&g_cur[d], 1);
    g_csrc[pos] = s;
}

// ---------------- f32x2 tiled GEMM (FFMA2), fp16 output --------------------
// BM=128, BN=64, BK=16, 256 threads. Row-pair packed accumulators.
__global__ __launch_bounds__(256) void gemm_f16out(const float* __restrict__ A,
                                                   const float* __restrict__ B,
                                                   __half* __restrict__ C,
                                                   int M, int N, int K) {
    __shared__ __align__(16) float As[16][130];   // [kk][m]
    __shared__ __align__(16) float Bs[16][68];    // [kk][n]
    int tid = threadIdx.x;
    int tx = tid & 15, ty = tid >> 4;
    int row0 = blockIdx.y * 128, col0 = blockIdx.x * 64;

    ull acc[4][4];
#pragma unroll
    for (int i = 0; i < 4; i++)
#pragma unroll
        for (int j = 0; j < 4; j++) acc[i][j] = 0ull;

    for (int k0 = 0; k0 < K; k0 += 16) {
        {
            int r = tid >> 2;            // 0..63
            int c4 = (tid & 3) * 4;      // 0,4,8,12
#pragma unroll
            for (int rr = 0; rr < 2; rr++) {
                int row = r + rr * 64;
                int gr = row0 + row;
                float4 v = make_float4(0.f, 0.f, 0.f, 0.f);
                if (gr < M) v = *(const float4*)&A[(size_t)gr * K + k0 + c4];
                As[c4 + 0][row] = v.x; As[c4 + 1][row] = v.y;
                As[c4 + 2][row] = v.z; As[c4 + 3][row] = v.w;
            }
        }
        {
            int r = tid >> 4;            // 0..15
            int c4 = (tid & 15) * 4;
            int gc = col0 + c4;
            float4 v;
            if (gc + 3 < N) {
                v = *(const float4*)&B[(size_t)(k0 + r) * N + gc];
            } else {
                v.x = (gc + 0 < N) ? B[(size_t)(k0 + r) * N + gc + 0] : 0.f;
                v.y = (gc + 1 < N) ? B[(size_t)(k0 + r) * N + gc + 1] : 0.f;
                v.z = (gc + 2 < N) ? B[(size_t)(k0 + r) * N + gc + 2] : 0.f;
                v.w = (gc + 3 < N) ? B[(size_t)(k0 + r) * N + gc + 3] : 0.f;
            }
            *(float4*)&Bs[r][c4] = v;
        }
        __syncthreads();
#pragma unroll
        for (int kk = 0; kk < 16; kk++) {
            float4 bq = *(const float4*)&Bs[kk][tx * 4];
            ull bd0 = dup2f(bq.x), bd1 = dup2f(bq.y), bd2 = dup2f(bq.z), bd3 = dup2f(bq.w);
            ull av[4];
#pragma unroll
            for (int i = 0; i < 4; i++)
                av[i] = *(const ull*)&As[kk][ty * 8 + 2 * i];
#pragma unroll
            for (int i = 0; i < 4; i++) {
                ffma2(acc[i][0], av[i], bd0);
                ffma2(acc[i][1], av[i], bd1);
                ffma2(acc[i][2], av[i], bd2);
                ffma2(acc[i][3], av[i], bd3);
            }
        }
        __syncthreads();
    }
    int gc = col0 + tx * 4;
    if (gc + 4 <= N) {
#pragma unroll
        for (int i = 0; i < 4; i++) {
            float2 c0 = unpk(acc[i][0]);
            float2 c1 = unpk(acc[i][1]);
            float2 c2 = unpk(acc[i][2]);
            float2 c3 = unpk(acc[i][3]);
            int gr0 = row0 + ty * 8 + 2 * i;
#pragma unroll
            for (int p = 0; p < 2; p++) {
                int gr = gr0 + p;
                if (gr >= M) continue;
                float f0 = p ? c0.y : c0.x, f1 = p ? c1.y : c1.x;
                float f2 = p ? c2.y : c2.x, f3 = p ? c3.y : c3.x;
                unsigned u0, u1;
                asm("cvt.rn.f16x2.f32 %0, %1, %2;" : "=r"(u0) : "f"(f1), "f"(f0));
                asm("cvt.rn.f16x2.f32 %0, %1, %2;" : "=r"(u1) : "f"(f3), "f"(f2));
                *(uint2*)(C + (size_t)gr * N + gc) = make_uint2(u0, u1);
            }
        }
    }
}

// ---------------- per-node attention logits, layer 1 ----------------
__global__ void k_ef1(const float* __restrict__ x) {
    __shared__ float xs[32][FIN + 4];
    __shared__ float M1[2][FIN * NH1];
    int n0 = blockIdx.x * 32;
    int tid = threadIdx.x;  // 256
    for (int i = tid; i < FIN * NH1; i += 256) {
        M1[0][i] = g_M1s[i];
        M1[1][i] = g_M1d[i];
    }
    for (int i = tid; i < 32 * FIN; i += 256) {
        int r = i / FIN, c = i % FIN;
        int gn = n0 + r;
        xs[r][c] = (gn < NN) ? x[(size_t)gn * FIN + c] : 0.f;
    }
    __syncthreads();
    int node = tid / 8, q = tid % 8;
    int h = q & 3;
    int isd = q >> 2;
    const float* M = M1[isd];
    float s = 0.f;
#pragma unroll 16
    for (int k = 0; k < FIN; k++) s += xs[node][k] * M[k * NH1 + h];
    int gn = n0 + node;
    if (gn < NN) {
        if (isd) g_ed1[gn * NH1 + h] = s;
        else     g_es1[gn * NH1 + h] = s;
    }
}

// ---------------- layer-1 aggregation: 1 warp per node, pipelined ----------
__global__ void k_agg1(const float* __restrict__ b1) {
    int warp = (blockIdx.x * blockDim.x + threadIdx.x) >> 5;
    if (warp >= NN) return;
    int lane = threadIdx.x & 31;
    int node = warp;
    int head = lane >> 3;
    int f0 = lane * 8;
    ull a2[4] = {0ull, 0ull, 0ull, 0ull};
    float s = 0.f;
    float edv = g_ed1[node * NH1 + head];
    int beg = g_off[node];
    int cnt = g_off[node + 1] - beg;
    const int* cs = g_csrc + beg;

    uint4 hv0, hv1;
    float ev0 = 0.f, ev1 = 0.f;
    if (cnt > 0) {
        int s0 = __ldg(&cs[0]);
        hv0 = __ldg((const uint4*)(g_h1h + (size_t)s0 * H1DIM + f0));
        ev0 = __ldg(&g_es1[s0 * NH1 + head]);
    }
    if (cnt > 1) {
        int s1 = __ldg(&cs[1]);
        hv1 = __ldg((const uint4*)(g_h1h + (size_t)s1 * H1DIM + f0));
        ev1 = __ldg(&g_es1[s1 * NH1 + head]);
    }
    int j = 0;
    for (; j + 1 < cnt; j += 2) {
        // consume slot 0, prefetch j+2
        {
            uint4 h = hv0; float es = ev0;
            if (j + 2 < cnt) {
                int sn = __ldg(&cs[j + 2]);
                hv0 = __ldg((const uint4*)(g_h1h + (size_t)sn * H1DIM + f0));
                ev0 = __ldg(&g_es1[sn * NH1 + head]);
            }
            float e = es + edv;
            e = (e > 0.f) ? e : 0.2f * e;
            float w = __expf(e);
            s += w;
            ull wd = dup2f(w);
            ffma2(a2[0], wd, h2f2(h.x));
            ffma2(a2[1], wd, h2f2(h.y));
            ffma2(a2[2], wd, h2f2(h.z));
            ffma2(a2[3], wd, h2f2(h.w));
        }
        // consume slot 1, prefetch j+3
        {
            uint4 h = hv1; float es = ev1;
            if (j + 3 < cnt) {
                int sn = __ldg(&cs[j + 3]);
                hv1 = __ldg((const uint4*)(g_h1h + (size_t)sn * H1DIM + f0));
                ev1 = __ldg(&g_es1[sn * NH1 + head]);
            }
            float e = es + edv;
            e = (e > 0.f) ? e : 0.2f * e;
            float w = __expf(e);
            s += w;
            ull wd = dup2f(w);
            ffma2(a2[0], wd, h2f2(h.x));
            ffma2(a2[1], wd, h2f2(h.y));
            ffma2(a2[2], wd, h2f2(h.z));
            ffma2(a2[3], wd, h2f2(h.w));
        }
    }
    if (j < cnt) {
        float e = ev0 + edv;
        e = (e > 0.f) ? e : 0.2f * e;
        float w = __expf(e);
        s += w;
        ull wd = dup2f(w);
        ffma2(a2[0], wd, h2f2(hv0.x));
        ffma2(a2[1], wd, h2f2(hv0.y));
        ffma2(a2[2], wd, h2f2(hv0.z));
        ffma2(a2[3], wd, h2f2(hv0.w));
    }
    float inv = 1.f / (s + 1e-16f);
    float o[8];
#pragma unroll
    for (int p = 0; p < 4; p++) {
        float2 v = unpk(a2[p]);
        o[2 * p + 0] = v.x; o[2 * p + 1] = v.y;
    }
    float4 q0, q1;
#pragma unroll
    for (int i = 0; i < 8; i++) {
        float v = o[i] * inv + b1[f0 + i];
        v = (v > 0.f) ? v : (__expf(v) - 1.f);        // ELU
        if (i < 4) (&q0.x)[i] = v; else (&q1.x)[i - 4] = v;
    }
    float4* op = (float4*)(g_o1 + (size_t)node * H1DIM + f0);
    op[0] = q0; op[1] = q1;
}

// ---------------- per-node attention logits, layer 2 ----------------
__global__ void k_ef2() {
    int warp = (blockIdx.x * blockDim.x + threadIdx.x) >> 5;
    if (warp >= NN) return;
    int lane = threadIdx.x & 31;
    const float* row = g_o1 + (size_t)warp * H1DIM;
    float ps = 0.f, pd = 0.f;
#pragma unroll
    for (int i = 0; i < 8; i++) {
        int k = lane + 32 * i;
        float v = row[k];
        ps += v * g_M2s[k];
        pd += v * g_M2d[k];
    }
#pragma unroll
    for (int o = 16; o > 0; o >>= 1) {
        ps += __shfl_xor_sync(0xffffffffu, ps, o);
        pd += __shfl_xor_sync(0xffffffffu, pd, o);
    }
    if (lane == 0) { g_es2[warp] = ps; g_ed2[warp] = pd; }
}

// ---------------- layer-2 aggregation: warp per node, pipelined ------------
__global__ void k_agg2(float* __restrict__ out) {
    int warp = (blockIdx.x * blockDim.x + threadIdx.x) >> 5;
    if (warp >= NN) return;
    int lane = threadIdx.x & 31;
    int node = warp;
    float a0 = 0.f, a1 = 0.f, s = 0.f;
    float edv = g_ed2[node];
    int beg = g_off[node];
    int cnt = g_off[node + 1] - beg;
    const int* cs = g_csrc + beg;

    float v00 = 0.f, v01 = 0.f, v10 = 0.f, v11 = 0.f;
    float ev0 = 0.f, ev1 = 0.f;
    if (cnt > 0) {
        int s0 = __ldg(&cs[0]);
        v00 = __half2float(__ldg(&g_h2h[(size_t)s0 * NC + lane]));
        v01 = (lane < 8) ? __half2float(__ldg(&g_h2h[(size_t)s0 * NC + 32 + lane])) : 0.f;
        ev0 = __ldg(&g_es2[s0]);
    }
    if (cnt > 1) {
        int s1 = __ldg(&cs[1]);
        v10 = __half2float(__ldg(&g_h2h[(size_t)s1 * NC + lane]));
        v11 = (lane < 8) ? __half2float(__ldg(&g_h2h[(size_t)s1 * NC + 32 + lane])) : 0.f;
        ev1 = __ldg(&g_es2[s1]);
    }
    int j = 0;
    for (; j + 1 < cnt; j += 2) {
        {
            float x0 = v00, x1 = v01, es = ev0;
            if (j + 2 < cnt) {
                int sn = __ldg(&cs[j + 2]);
                v00 = __half2float(__ldg(&g_h2h[(size_t)sn * NC + lane]));
                v01 = (lane < 8) ? __half2float(__ldg(&g_h2h[(size_t)sn * NC + 32 + lane])) : 0.f;
                ev0 = __ldg(&g_es2[sn]);
            }
            float e = es + edv;
            e = (e > 0.f) ? e : 0.2f * e;
            float w = __expf(e);
            s += w; a0 += w * x0; a1 += w * x1;
        }
        {
            float x0 = v10, x1 = v11, es = ev1;
            if (j + 3 < cnt) {
                int sn = __ldg(&cs[j + 3]);
                v10 = __half2float(__ldg(&g_h2h[(size_t)sn * NC + lane]));
                v11 = (lane < 8) ? __half2float(__ldg(&g_h2h[(size_t)sn * NC + 32 + lane])) : 0.f;
                ev1 = __ldg(&g_es2[sn]);
            }
            float e = es + edv;
            e = (e > 0.f) ? e : 0.2f * e;
            float w = __expf(e);
            s += w; a0 += w * x0; a1 += w * x1;
        }
    }
    if (j < cnt) {
        float e = ev0 + edv;
        e = (e > 0.f) ? e : 0.2f * e;
        float w = __expf(e);
        s += w; a0 += w * v00; a1 += w * v01;
    }
    float inv = 1.f / (s + 1e-16f);
    out[(size_t)node * NC + lane] = a0 * inv;
    if (lane < 8) out[(size_t)node * NC + 32 + lane] = a1 * inv;
}

// ---------------- host launcher ----------------
extern "C" void kernel_launch(void* const* d_in, const int* in_sizes, int n_in,
                              void* d_out, int out_size) {
    const float* x   = (const float*)d_in[0];
    const void*  ei  = d_in[1];
    const float* W1  = (const float*)d_in[2];
    const float* b1  = (const float*)d_in[3];
    const float* B1  = (const float*)d_in[4];
    const float* cs1 = (const float*)d_in[5];
    const float* cd1 = (const float*)d_in[6];
    const float* W2  = (const float*)d_in[7];
    const float* B2  = (const float*)d_in[8];
    const float* cs2 = (const float*)d_in[9];
    const float* cd2 = (const float*)d_in[10];
    float* out = (float*)d_out;

    void *p_h1 = nullptr, *p_o1 = nullptr, *p_h2 = nullptr;
    cudaGetSymbolAddress(&p_h1, g_h1h);
    cudaGetSymbolAddress(&p_o1, g_o1);
    cudaGetSymbolAddress(&p_h2, g_h2h);

    k_misc<<<1, 512>>>(ei, B1, cs1, cd1, B2, cs2, cd2);
    k_hist<<<(NE + 255) / 256, 256>>>(ei);
    k_scan<<<1, 1024>>>();
    k_scatter<<<(NE + 255) / 256, 256>>>(ei);

    // layer 1
    gemm_f16out<<<dim3(4, (NN + 127) / 128), 256>>>(x, W1, (__half*)p_h1,
                                                    NN, H1DIM, FIN);
    k_ef1<<<(NN + 31) / 32, 256>>>(x);
    k_agg1<<<(NN + 7) / 8, 256>>>(b1);

    // layer 2
    gemm_f16out<<<dim3(1, (NN + 127) / 128), 256>>>((const float*)p_o1, W2,
                                                    (__half*)p_h2, NN, NC, H1DIM);
    k_ef2<<<(NN + 7) / 8, 256>>>();
    k_agg2<<<(NN + 7) / 8, 256>>>(out);
}

// round 13
// speedup vs baseline: 1.3700x; 1.0395x over previous
#include <cuda_runtime.h>
#include <cuda_fp16.h>
#include <cstdint>

#define NN 50000
#define NE 800000
#define FIN 128
#define H1DIM 256   // NHEAD*NHID
#define NH1 4
#define NB 8
#define NC 40

typedef unsigned long long ull;

__device__ __forceinline__ ull dup2f(float x) {
    unsigned u = __float_as_uint(x);
    ull r; asm("mov.b64 %0, {%1, %1};" : "=l"(r) : "r"(u)); return r;
}
__device__ __forceinline__ void ffma2(ull& d, ull a, ull b) {
    asm("fma.rn.f32x2 %0, %1, %2, %0;" : "+l"(d) : "l"(a), "l"(b));
}
__device__ __forceinline__ float2 unpk(ull v) {
    unsigned lo, hi;
    asm("mov.b64 {%0, %1}, %2;" : "=r"(lo), "=r"(hi) : "l"(v));
    return make_float2(__uint_as_float(lo), __uint_as_float(hi));
}
__device__ __forceinline__ ull pk2(float x, float y) {
    ull r;
    asm("mov.b64 %0, {%1, %2};" : "=l"(r) : "r"(__float_as_uint(x)), "r"(__float_as_uint(y)));
    return r;
}
// two f16 packed in u -> packed f32x2
__device__ __forceinline__ ull h2f2(unsigned u) {
    float2 f = __half22float2(*(__half2*)&u);
    return pk2(f.x, f.y);
}

// ---------------- scratch (device globals; allocation-free) ----------------
__device__ __half g_h1h[(size_t)NN * H1DIM];  // x @ W1 (fp16)
__device__ __half g_o1h[(size_t)NN * H1DIM];  // layer-1 out (fp16)
__device__ __half g_h2h[(size_t)NN * NC];     // o1 @ W2 (fp16)
__device__ float g_es1[NN * NH1], g_ed1[NN * NH1];
__device__ float g_es2[NN], g_ed2[NN];
__device__ int   g_deg[NN];
__device__ int   g_off[NN + 1];
__device__ int   g_cur[NN];
__device__ int   g_csrc[NE];
__device__ float g_M1s[FIN * NH1], g_M1d[FIN * NH1];
__device__ float g_M2s[H1DIM], g_M2d[H1DIM];
__device__ int   g_is64;

// ---------------- misc ----------------
__global__ void k_misc(const void* ei, const float* __restrict__ B1,
                       const float* __restrict__ cs1, const float* __restrict__ cd1,
                       const float* __restrict__ B2, const float* __restrict__ cs2,
                       const float* __restrict__ cd2) {
    int tid = threadIdx.x;
    if (tid == 0) {
        const unsigned* w = (const unsigned*)ei;
        int is64 = 1;
        for (int i = 0; i < 64; i++) {
            if (w[2 * i + 1] != 0u) { is64 = 0; break; }
        }
        g_is64 = is64;
    }
    for (int i = tid; i < FIN * NH1; i += blockDim.x) {
        int k = i / NH1, h = i % NH1;
        float ss = 0.f, sd = 0.f;
        for (int j = 0; j < NB; j++) {
            float b = B1[k * NB + j];
            ss += b * cs1[j * NH1 + h];
            sd += b * cd1[j * NH1 + h];
        }
        g_M1s[i] = ss; g_M1d[i] = sd;
    }
    for (int i = tid; i < H1DIM; i += blockDim.x) {
        float ss = 0.f, sd = 0.f;
        for (int j = 0; j < NB; j++) {
            float b = B2[i * NB + j];
            ss += b * cs2[j];
            sd += b * cd2[j];
        }
        g_M2s[i] = ss; g_M2d[i] = sd;
    }
    for (int i = tid; i < NN; i += blockDim.x) g_deg[i] = 0;
}

// ---------------- CSR build (32-bit loads only) ----------------
__global__ void k_hist(const void* ei) {
    int e = blockIdx.x * blockDim.x + threadIdx.x;
    if (e >= NE) return;
    const int* p = (const int*)ei;
    int d = g_is64 ? p[2 * (NE + e)] : p[NE + e];
    atomicAdd(&g_deg[d], 1);
}

__global__ void k_scan() {  // single block, 1024 threads
    __shared__ int part[1024];
    int tid = threadIdx.x;
    const int per = (NN + 1023) / 1024;
    int start = tid * per;
    int end = start + per; if (end > NN) end = NN;
    if (start > NN) start = NN;
    int s = 0;
    for (int i = start; i < end; i++) s += g_deg[i];
    part[tid] = s;
    __syncthreads();
    for (int off = 1; off < 1024; off <<= 1) {
        int v = (tid >= off) ? part[tid - off] : 0;
        __syncthreads();
        part[tid] += v;
        __syncthreads();
    }
    int run = (tid > 0) ? part[tid - 1] : 0;
    for (int i = start; i < end; i++) {
        g_off[i] = run; g_cur[i] = run;
        run += g_deg[i];
    }
    if (tid == 1023) g_off[NN] = part[1023];
}

__global__ void k_scatter(const void* ei) {
    int e = blockIdx.x * blockDim.x + threadIdx.x;
    if (e >= NE) return;
    const int* p = (const int*)ei;
    int s, d;
    if (g_is64) { s = p[2 * e]; d = p[2 * (NE + e)]; }
    else        { s = p[e];     d = p[NE + e]; }
    int pos = atomicAdd(&g_cur[d], 1);
    g_csrc[pos] = s;
}

// ---------------- f32x2 tiled GEMM (FFMA2), f32 A, fp16 out — layer 1 ------
// BM=128, BN=64, BK=16, 256 threads. Row-pair packed accumulators.
__global__ __launch_bounds__(256) void gemm_f16out(const float* __restrict__ A,
                                                   const float* __restrict__ B,
                                                   __half* __restrict__ C,
                                                   int M, int N, int K) {
    __shared__ __align__(16) float As[16][130];   // [kk][m]
    __shared__ __align__(16) float Bs[16][68];    // [kk][n]
    int tid = threadIdx.x;
    int tx = tid & 15, ty = tid >> 4;
    int row0 = blockIdx.y * 128, col0 = blockIdx.x * 64;

    ull acc[4][4];
#pragma unroll
    for (int i = 0; i < 4; i++)
#pragma unroll
        for (int j = 0; j < 4; j++) acc[i][j] = 0ull;

    for (int k0 = 0; k0 < K; k0 += 16) {
        {
            int r = tid >> 2;            // 0..63
            int c4 = (tid & 3) * 4;      // 0,4,8,12
#pragma unroll
            for (int rr = 0; rr < 2; rr++) {
                int row = r + rr * 64;
                int gr = row0 + row;
                float4 v = make_float4(0.f, 0.f, 0.f, 0.f);
                if (gr < M) v = *(const float4*)&A[(size_t)gr * K + k0 + c4];
                As[c4 + 0][row] = v.x; As[c4 + 1][row] = v.y;
                As[c4 + 2][row] = v.z; As[c4 + 3][row] = v.w;
            }
        }
        {
            int r = tid >> 4;            // 0..15
            int c4 = (tid & 15) * 4;
            int gc = col0 + c4;
            float4 v;
            if (gc + 3 < N) {
                v = *(const float4*)&B[(size_t)(k0 + r) * N + gc];
            } else {
                v.x = (gc + 0 < N) ? B[(size_t)(k0 + r) * N + gc + 0] : 0.f;
                v.y = (gc + 1 < N) ? B[(size_t)(k0 + r) * N + gc + 1] : 0.f;
                v.z = (gc + 2 < N) ? B[(size_t)(k0 + r) * N + gc + 2] : 0.f;
                v.w = (gc + 3 < N) ? B[(size_t)(k0 + r) * N + gc + 3] : 0.f;
            }
            *(float4*)&Bs[r][c4] = v;
        }
        __syncthreads();
#pragma unroll
        for (int kk = 0; kk < 16; kk++) {
            float4 bq = *(const float4*)&Bs[kk][tx * 4];
            ull bd0 = dup2f(bq.x), bd1 = dup2f(bq.y), bd2 = dup2f(bq.z), bd3 = dup2f(bq.w);
            ull av[4];
#pragma unroll
            for (int i = 0; i < 4; i++)
                av[i] = *(const ull*)&As[kk][ty * 8 + 2 * i];
#pragma unroll
            for (int i = 0; i < 4; i++) {
                ffma2(acc[i][0], av[i], bd0);
                ffma2(acc[i][1], av[i], bd1);
                ffma2(acc[i][2], av[i], bd2);
                ffma2(acc[i][3], av[i], bd3);
            }
        }
        __syncthreads();
    }
    int gc = col0 + tx * 4;
    if (gc + 4 <= N) {
#pragma unroll
        for (int i = 0; i < 4; i++) {
            float2 c0 = unpk(acc[i][0]);
            float2 c1 = unpk(acc[i][1]);
            float2 c2 = unpk(acc[i][2]);
            float2 c3 = unpk(acc[i][3]);
            int gr0 = row0 + ty * 8 + 2 * i;
#pragma unroll
            for (int p = 0; p < 2; p++) {
                int gr = gr0 + p;
                if (gr >= M) continue;
                float f0 = p ? c0.y : c0.x, f1 = p ? c1.y : c1.x;
                float f2 = p ? c2.y : c2.x, f3 = p ? c3.y : c3.x;
                unsigned u0, u1;
                asm("cvt.rn.f16x2.f32 %0, %1, %2;" : "=r"(u0) : "f"(f1), "f"(f0));
                asm("cvt.rn.f16x2.f32 %0, %1, %2;" : "=r"(u1) : "f"(f3), "f"(f2));
                *(uint2*)(C + (size_t)gr * N + gc) = make_uint2(u0, u1);
            }
        }
    }
}

// ---------------- same GEMM but fp16 A — layer 2 (A = o1 fp16) -------------
__global__ __launch_bounds__(256) void gemm_f16in(const __half* __restrict__ A,
                                                  const float* __restrict__ B,
                                                  __half* __restrict__ C,
                                                  int M, int N, int K) {
    __shared__ __align__(16) float As[16][130];
    __shared__ __align__(16) float Bs[16][68];
    int tid = threadIdx.x;
    int tx = tid & 15, ty = tid >> 4;
    int row0 = blockIdx.y * 128, col0 = blockIdx.x * 64;

    ull acc[4][4];
#pragma unroll
    for (int i = 0; i < 4; i++)
#pragma unroll
        for (int j = 0; j < 4; j++) acc[i][j] = 0ull;

    for (int k0 = 0; k0 < K; k0 += 16) {
        {
            int r = tid >> 2;            // 0..63
            int c4 = (tid & 3) * 4;      // 0,4,8,12
#pragma unroll
            for (int rr = 0; rr < 2; rr++) {
                int row = r + rr * 64;
                int gr = row0 + row;
                float2 va = make_float2(0.f, 0.f), vb = make_float2(0.f, 0.f);
                if (gr < M) {
                    uint2 u = *(const uint2*)&A[(size_t)gr * K + k0 + c4];
                    va = __half22float2(*(__half2*)&u.x);
                    vb = __half22float2(*(__half2*)&u.y);
                }
                As[c4 + 0][row] = va.x; As[c4 + 1][row] = va.y;
                As[c4 + 2][row] = vb.x; As[c4 + 3][row] = vb.y;
            }
        }
        {
            int r = tid >> 4;            // 0..15
            int c4 = (tid & 15) * 4;
            int gc = col0 + c4;
            float4 v;
            if (gc + 3 < N) {
                v = *(const float4*)&B[(size_t)(k0 + r) * N + gc];
            } else {
                v.x = (gc + 0 < N) ? B[(size_t)(k0 + r) * N + gc + 0] : 0.f;
                v.y = (gc + 1 < N) ? B[(size_t)(k0 + r) * N + gc + 1] : 0.f;
                v.z = (gc + 2 < N) ? B[(size_t)(k0 + r) * N + gc + 2] : 0.f;
                v.w = (gc + 3 < N) ? B[(size_t)(k0 + r) * N + gc + 3] : 0.f;
            }
            *(float4*)&Bs[r][c4] = v;
        }
        __syncthreads();
#pragma unroll
        for (int kk = 0; kk < 16; kk++) {
            float4 bq = *(const float4*)&Bs[kk][tx * 4];
            ull bd0 = dup2f(bq.x), bd1 = dup2f(bq.y), bd2 = dup2f(bq.z), bd3 = dup2f(bq.w);
            ull av[4];
#pragma unroll
            for (int i = 0; i < 4; i++)
                av[i] = *(const ull*)&As[kk][ty * 8 + 2 * i];
#pragma unroll
            for (int i = 0; i < 4; i++) {
                ffma2(acc[i][0], av[i], bd0);
                ffma2(acc[i][1], av[i], bd1);
                ffma2(acc[i][2], av[i], bd2);
                ffma2(acc[i][3], av[i], bd3);
            }
        }
        __syncthreads();
    }
    int gc = col0 + tx * 4;
    if (gc + 4 <= N) {
#pragma unroll
        for (int i = 0; i < 4; i++) {
            float2 c0 = unpk(acc[i][0]);
            float2 c1 = unpk(acc[i][1]);
            float2 c2 = unpk(acc[i][2]);
            float2 c3 = unpk(acc[i][3]);
            int gr0 = row0 + ty * 8 + 2 * i;
#pragma unroll
            for (int p = 0; p < 2; p++) {
                int gr = gr0 + p;
                if (gr >= M) continue;
                float f0 = p ? c0.y : c0.x, f1 = p ? c1.y : c1.x;
                float f2 = p ? c2.y : c2.x, f3 = p ? c3.y : c3.x;
                unsigned u0, u1;
                asm("cvt.rn.f16x2.f32 %0, %1, %2;" : "=r"(u0) : "f"(f1), "f"(f0));
                asm("cvt.rn.f16x2.f32 %0, %1, %2;" : "=r"(u1) : "f"(f3), "f"(f2));
                *(uint2*)(C + (size_t)gr * N + gc) = make_uint2(u0, u1);
            }
        }
    }
}

// ---------------- per-node attention logits, layer 1 ----------------
__global__ void k_ef1(const float* __restrict__ x) {
    __shared__ float xs[32][FIN + 4];
    __shared__ float M1[2][FIN * NH1];
    int n0 = blockIdx.x * 32;
    int tid = threadIdx.x;  // 256
    for (int i = tid; i < FIN * NH1; i += 256) {
        M1[0][i] = g_M1s[i];
        M1[1][i] = g_M1d[i];
    }
    for (int i = tid; i < 32 * FIN; i += 256) {
        int r = i / FIN, c = i % FIN;
        int gn = n0 + r;
        xs[r][c] = (gn < NN) ? x[(size_t)gn * FIN + c] : 0.f;
    }
    __syncthreads();
    int node = tid / 8, q = tid % 8;
    int h = q & 3;
    int isd = q >> 2;
    const float* M = M1[isd];
    float s = 0.f;
#pragma unroll 16
    for (int k = 0; k < FIN; k++) s += xs[node][k] * M[k * NH1 + h];
    int gn = n0 + node;
    if (gn < NN) {
        if (isd) g_ed1[gn * NH1 + h] = s;
        else     g_es1[gn * NH1 + h] = s;
    }
}

// ---------------- layer-1 aggregation (+ folded ef2) -----------------------
// 1 warp per dst node; lane covers 8 feats; fp16 gather, f32x2 accumulate.
__global__ void k_agg1(const float* __restrict__ b1) {
    int warp = (blockIdx.x * blockDim.x + threadIdx.x) >> 5;
    if (warp >= NN) return;
    int lane = threadIdx.x & 31;
    int node = warp;
    int head = lane >> 3;
    int f0 = lane * 8;
    ull a2[4] = {0ull, 0ull, 0ull, 0ull};
    float s = 0.f;
    float edv = g_ed1[node * NH1 + head];
    int beg = g_off[node], end = g_off[node + 1];
    int src_n = (beg < end) ? g_csrc[beg] : 0;
    for (int j = beg; j < end; j++) {
        int src = src_n;
        if (j + 1 < end) src_n = g_csrc[j + 1];
        float e = g_es1[src * NH1 + head] + edv;
        e = (e > 0.f) ? e : 0.2f * e;                 // leaky_relu
        float w = __expf(e);
        s += w;
        ull wd = dup2f(w);
        uint4 hv = *(const uint4*)(g_h1h + (size_t)src * H1DIM + f0);
        ffma2(a2[0], wd, h2f2(hv.x));
        ffma2(a2[1], wd, h2f2(hv.y));
        ffma2(a2[2], wd, h2f2(hv.z));
        ffma2(a2[3], wd, h2f2(hv.w));
    }
    float inv = 1.f / (s + 1e-16f);
    float o[8];
#pragma unroll
    for (int p = 0; p < 4; p++) {
        float2 v = unpk(a2[p]);
        o[2 * p + 0] = v.x; o[2 * p + 1] = v.y;
    }
    float4 bb0 = *(const float4*)(b1 + f0);
    float4 bb1 = *(const float4*)(b1 + f0 + 4);
    float ps = 0.f, pd = 0.f;
    unsigned hh[4];
#pragma unroll
    for (int i = 0; i < 8; i++) {
        float v = o[i] * inv + ((i < 4) ? (&bb0.x)[i] : (&bb1.x)[i - 4]);
        v = (v > 0.f) ? v : (__expf(v) - 1.f);        // ELU
        o[i] = v;
        ps += v * g_M2s[f0 + i];                      // folded ef2 (fp32, pre-rounding)
        pd += v * g_M2d[f0 + i];
    }
#pragma unroll
    for (int p = 0; p < 4; p++) {
        asm("cvt.rn.f16x2.f32 %0, %1, %2;" : "=r"(hh[p]) : "f"(o[2 * p + 1]), "f"(o[2 * p]));
    }
    *(uint4*)(g_o1h + (size_t)node * H1DIM + f0) = make_uint4(hh[0], hh[1], hh[2], hh[3]);
#pragma unroll
    for (int ofs = 16; ofs > 0; ofs >>= 1) {
        ps += __shfl_xor_sync(0xffffffffu, ps, ofs);
        pd += __shfl_xor_sync(0xffffffffu, pd, ofs);
    }
    if (lane == 0) { g_es2[node] = ps; g_ed2[node] = pd; }
}

// ---------------- layer-2 aggregation: warp per dst node -------------------
__global__ void k_agg2(float* __restrict__ out) {
    int warp = (blockIdx.x * blockDim.x + threadIdx.x) >> 5;
    if (warp >= NN) return;
    int lane = threadIdx.x & 31;
    int node = warp;
    float a0 = 0.f, a1 = 0.f, s = 0.f;
    float edv = g_ed2[node];
    int beg = g_off[node], end = g_off[node + 1];
    int src_n = (beg < end) ? g_csrc[beg] : 0;
    for (int j = beg; j < end; j++) {
        int src = src_n;
        if (j + 1 < end) src_n = g_csrc[j + 1];
        float e = g_es2[src] + edv;
        e = (e > 0.f) ? e : 0.2f * e;
        float w = __expf(e);
        float v0 = __half2float(g_h2h[(size_t)src * NC + lane]);
        float v1 = (lane < 8) ? __half2float(g_h2h[(size_t)src * NC + 32 + lane]) : 0.f;
        s += w;
        a0 += w * v0;
        a1 += w * v1;
    }
    float inv = 1.f / (s + 1e-16f);
    out[(size_t)node * NC + lane] = a0 * inv;
    if (lane < 8) out[(size_t)node * NC + 32 + lane] = a1 * inv;
}

// ---------------- host launcher ----------------
extern "C" void kernel_launch(void* const* d_in, const int* in_sizes, int n_in,
                              void* d_out, int out_size) {
    const float* x   = (const float*)d_in[0];
    const void*  ei  = d_in[1];
    const float* W1  = (const float*)d_in[2];
    const float* b1  = (const float*)d_in[3];
    const float* B1  = (const float*)d_in[4];
    const float* cs1 = (const float*)d_in[5];
    const float* cd1 = (const float*)d_in[6];
    const float* W2  = (const float*)d_in[7];
    const float* B2  = (const float*)d_in[8];
    const float* cs2 = (const float*)d_in[9];
    const float* cd2 = (const float*)d_in[10];
    float* out = (float*)d_out;

    void *p_h1 = nullptr, *p_o1 = nullptr, *p_h2 = nullptr;
    cudaGetSymbolAddress(&p_h1, g_h1h);
    cudaGetSymbolAddress(&p_o1, g_o1h);
    cudaGetSymbolAddress(&p_h2, g_h2h);

    k_misc<<<1, 512>>>(ei, B1, cs1, cd1, B2, cs2, cd2);
    k_hist<<<(NE + 255) / 256, 256>>>(ei);
    k_scan<<<1, 1024>>>();
    k_scatter<<<(NE + 255) / 256, 256>>>(ei);

    // layer 1
    gemm_f16out<<<dim3(4, (NN + 127) / 128), 256>>>(x, W1, (__half*)p_h1,
                                                    NN, H1DIM, FIN);
    k_ef1<<<(NN + 31) / 32, 256>>>(x);
    k_agg1<<<(NN + 7) / 8, 256>>>(b1);

    // layer 2 (ef2 folded into k_agg1)
    gemm_f16in<<<dim3(1, (NN + 127) / 128), 256>>>((const __half*)p_o1, W2,
                                                   (__half*)p_h2, NN, NC, H1DIM);
    k_agg2<<<(NN + 7) / 8, 256>>>(out);
}